// round 4
// baseline (speedup 1.0000x reference)
#include <cuda_runtime.h>
#include <cstdint>

#define SS 30
#define SP 900          // 30*30
#define S4 810000       // 30^4
#define NB 2

typedef unsigned long long ull;

// t1: [b][br][cipair5][h1w1][pos][2]  (lanes = ci even/odd)  — float2 elements
__device__ __align__(16) float g_t1[NB * 2 * 5 * SP * SP * 2];
// t2: [b][co10][h1w1][pos][br2]  — float2 elements (lanes = branch A/B)
__device__ __align__(16) float g_t2[NB * 10 * SP * SP * 2];
// Weights
__device__ __align__(16) float g_W1[9 * 9 * 20];                 // [to][ti][co20]
__device__ __align__(16) float g_W2[2 * 9 * 5 * 9 * 10 * 2];     // [br][to][cp][ti][co][ci-lane]
__device__ __align__(16) float g_W3[9 * 10 * 9 * 2];             // [to][ci][ti][br2]

#define PACK2(d, a, b)  asm("mov.b64 %0, {%1, %2};" : "=l"(d) : "f"(a), "f"(b))
#define FMA2(d, a, b)   asm("fma.rn.f32x2 %0, %1, %2, %0;" : "+l"(d) : "l"(a), "l"(b))
#define ADD2(d, a, b)   asm("add.rn.f32x2 %0, %1, %2;" : "=l"(d) : "l"(a), "l"(b))
#define UNPACK2(lo, hi, d) asm("mov.b64 {%0, %1}, %2;" : "=f"(lo), "=f"(hi) : "l"(d))

__device__ __forceinline__ uint32_t s2u(const void* p) {
    uint32_t a;
    asm("{ .reg .u64 t; cvta.to.shared.u64 t, %1; cvt.u32.u64 %0, t; }"
        : "=r"(a) : "l"(p));
    return a;
}
__device__ __forceinline__ void cpa4(uint32_t s, const void* g, int srcsz) {
    asm volatile("cp.async.ca.shared.global [%0], [%1], 4, %2;"
                 :: "r"(s), "l"(g), "r"(srcsz));
}
__device__ __forceinline__ void cpa16(uint32_t s, const void* g, int srcsz) {
    asm volatile("cp.async.ca.shared.global [%0], [%1], 16, %2;"
                 :: "r"(s), "l"(g), "r"(srcsz));
}
__device__ __forceinline__ void cpa_commit_wait() {
    asm volatile("cp.async.commit_group;");
    asm volatile("cp.async.wait_group 0;" ::: "memory");
}

// ---------------------------------------------------------------------------
// Weight prep.
// ---------------------------------------------------------------------------
__global__ void prep_kernel(const float* __restrict__ w1,
                            const float* __restrict__ w2,
                            const float* __restrict__ w3) {
    int tid = blockIdx.x * blockDim.x + threadIdx.x;
    int stride = gridDim.x * blockDim.x;
    for (int i = tid; i < 9 * 9 * 20; i += stride) {
        int co = i % 20;
        int ti = (i / 20) % 9;
        int to = i / 180;
        g_W1[i] = (co < 10) ? w1[co * 81 + to * 9 + ti]
                            : w1[(co - 10) * 81 + ti * 9 + to];
    }
    // W2: [br][to][cp][ti][co][lane], lane = ci parity, ci = 2*cp+lane
    for (int i = tid; i < 16200; i += stride) {
        int lane = i & 1;
        int j = i >> 1;
        int co = j % 10;
        int ti = (j / 10) % 9;
        int cp = (j / 90) % 5;
        int to = (j / 450) % 9;
        int br = j / 4050;
        int ci = 2 * cp + lane;
        int tap = br ? (ti * 9 + to) : (to * 9 + ti);
        g_W2[i] = w2[(co * 10 + ci) * 81 + tap];
    }
    for (int i = tid; i < 1620; i += stride) {
        int br = i % 2;
        int ti = (i / 2) % 9;
        int ci = (i / 18) % 10;
        int to = i / 180;
        g_W3[i] = (br == 0) ? w3[ci * 81 + to * 9 + ti]
                            : w3[ci * 81 + ti * 9 + to];
    }
}

// ---------------------------------------------------------------------------
// conv1: x (1 ch) -> t1 (ci-pair interleaved), relu.  One CTA per (b,h1,w1).
// ---------------------------------------------------------------------------
__global__ __launch_bounds__(300)
void conv1_kernel(const float* __restrict__ x, const float* __restrict__ b1) {
    __shared__ __align__(16) float sIn[32 * 33];
    __shared__ __align__(16) float sW[9 * 9 * 20];
    __shared__ float sB[20];
    int bid = blockIdx.x;
    int b = bid / SP;
    int rem = bid % SP;
    int h1 = rem / SS, w1 = rem % SS;
    int tid = threadIdx.x;

    {
        const float4* src = (const float4*)g_W1;
        float4* dst = (float4*)sW;
        for (int i = tid; i < 405; i += 300) dst[i] = src[i];
    }
    if (tid < 20) sB[tid] = b1[tid % 10];
    for (int i = tid; i < 32 * 33; i += 300) sIn[i] = 0.f;

    int h2 = tid / 10;
    int w2_0 = (tid % 10) * 3;

    int gOff[3], sOff[3];
#pragma unroll
    for (int k = 0; k < 3; k++) {
        int j = tid + k * 300;
        int rr = j / SS, cc = j % SS;
        gOff[k] = j;
        sOff[k] = (rr + 1) * 33 + cc + 1;
    }
    uint32_t sInA = s2u(sIn);

    ull acc[10][3];
#pragma unroll
    for (int c = 0; c < 10; c++)
#pragma unroll
        for (int p = 0; p < 3; p++) acc[c][p] = 0ull;

    const float* xb = x + (size_t)b * S4;

#pragma unroll 1
    for (int to = 0; to < 9; to++) {
        int H = h1 + to / 3 - 1, W = w1 + to % 3 - 1;
        bool ok = ((unsigned)H < SS) && ((unsigned)W < SS);
        int srcsz = ok ? 4 : 0;
        int poff = ok ? (H * SS + W) * SP : 0;
        const float* plane = xb + poff;
        __syncthreads();
#pragma unroll
        for (int k = 0; k < 3; k++)
            cpa4(sInA + sOff[k] * 4, plane + gOff[k], srcsz);
        cpa_commit_wait();
        __syncthreads();
#pragma unroll
        for (int dh2 = 0; dh2 < 3; dh2++) {
            const float* row = &sIn[(h2 + dh2) * 33 + w2_0];
            ull dup[5];
#pragma unroll
            for (int j = 0; j < 5; j++) { float v = row[j]; PACK2(dup[j], v, v); }
#pragma unroll
            for (int dw2 = 0; dw2 < 3; dw2++) {
                const ull* wp = (const ull*)(sW + (to * 9 + dh2 * 3 + dw2) * 20);
#pragma unroll
                for (int c = 0; c < 10; c++) {
                    ull w = wp[c];
#pragma unroll
                    for (int p = 0; p < 3; p++) FMA2(acc[c][p], dup[p + dw2], w);
                }
            }
        }
    }

    // store: pair c -> (br = c/5, cp = c%5), lanes = (co even, co odd) = ci lanes of t1
#pragma unroll
    for (int c = 0; c < 10; c++) {
        int br = c / 5, cp = c % 5;
        float b0 = sB[2 * c], b1v = sB[2 * c + 1];
        float2* d = (float2*)g_t1 +
                    (((size_t)(b * 2 + br) * 5 + cp) * SP + h1 * SS + w1) * SP +
                    h2 * SS + w2_0;
#pragma unroll
        for (int p = 0; p < 3; p++) {
            float lo, hi;
            UNPACK2(lo, hi, acc[c][p]);
            lo += b0; hi += b1v;
            d[p] = make_float2(lo > 0.f ? lo : 0.f, hi > 0.f ? hi : 0.f);
        }
    }
}

// ---------------------------------------------------------------------------
// conv2: t1 (ci-pair float2) -> t2 (branch-interleaved), relu.
// One CTA per (b, br, h1, w1), 300 threads = 2 co-halves x (30 h2 x 5 w2grp(6)).
// f32x2 lanes carry ci-parity partials: input LDS.64 + weight LDS.64, no packs.
// smem: 5 planes, 32 rows x 34 float2, left border 2 (16B-aligned staging).
// ---------------------------------------------------------------------------
__global__ __launch_bounds__(300, 2)
void conv2_kernel(const float* __restrict__ b2) {
    extern __shared__ __align__(16) char sm2[];
    ull* sIn = (ull*)sm2;                       // 5 * 1088 float2
    float* sW = (float*)(sm2 + 5 * 1088 * 8);   // 8100 floats
    __shared__ float sB[10];

    int bid = blockIdx.x;
    int w1 = bid % SS;
    int t = bid / SS;
    int h1 = t % SS;
    t /= SS;
    int br = t & 1;
    int b = t >> 1;
    int tid = threadIdx.x;

    {
        const float4* src = (const float4*)(g_W2 + br * 8100);
        float4* dst = (float4*)sW;
        for (int i = tid; i < 2025; i += 300) dst[i] = src[i];
    }
    if (tid < 10) sB[tid] = b2[tid];
    for (int i = tid; i < 5440; i += 300) sIn[i] = 0ull;

    int cohalf = tid / 150;
    int r = tid % 150;
    int h2 = r / 5;
    int w2_0 = (r % 5) * 6;
    int co0 = cohalf * 5;

    // staging role: (plane cp, row, half-row of 16B chunks)
    int scp = tid / 60;
    int srem = tid % 60;
    int srow = srem / 2;
    int shalf = srem % 2;
    int scount = shalf ? 7 : 8;
    const float2* t1f2 = (const float2*)g_t1 + (size_t)(b * 2 + br) * 5 * (size_t)S4;
    size_t gRow = (size_t)scp * S4 + srow * 30 + shalf * 16;   // float2 units
    uint32_t sRow = s2u(sIn) + (uint32_t)(scp * 1088 + (srow + 1) * 34 + 2) * 8 +
                    shalf * 128;

    ull acc[5][6];
#pragma unroll
    for (int c = 0; c < 5; c++)
#pragma unroll
        for (int p = 0; p < 6; p++) acc[c][p] = 0ull;

#pragma unroll 1
    for (int to = 0; to < 9; to++) {
        int H = h1 + to / 3 - 1, W = w1 + to % 3 - 1;
        bool ok = ((unsigned)H < SS) && ((unsigned)W < SS);
        int srcsz = ok ? 16 : 0;
        int poff = ok ? (H * SS + W) : 0;
        __syncthreads();
        const float2* g = t1f2 + gRow + (size_t)poff * SP;
#pragma unroll
        for (int k = 0; k < 8; k++)
            if (k < scount) cpa16(sRow + k * 16, g + k * 2, srcsz);
        cpa_commit_wait();
        __syncthreads();
#pragma unroll 1
        for (int cp = 0; cp < 5; cp++) {
            const ull* sc = sIn + cp * 1088;
            const ull* wbase = (const ull*)sW + (to * 5 + cp) * 90;
#pragma unroll
            for (int dh2 = 0; dh2 < 3; dh2++) {
                const ull* rowp = sc + (h2 + dh2) * 34 + 1 + w2_0;
                ull a[8];
#pragma unroll
                for (int j = 0; j < 8; j++) a[j] = rowp[j];
#pragma unroll
                for (int dw2 = 0; dw2 < 3; dw2++) {
                    const ull* wp = wbase + (dh2 * 3 + dw2) * 10 + co0;
#pragma unroll
                    for (int c = 0; c < 5; c++) {
                        ull w = wp[c];
#pragma unroll
                        for (int p = 0; p < 6; p++) FMA2(acc[c][p], a[p + dw2], w);
                    }
                }
            }
        }
    }

    int pos0 = h2 * SS + w2_0;
#pragma unroll
    for (int c = 0; c < 5; c++) {
        int co = co0 + c;
        float bias = sB[co];
        float* d = g_t2 + ((size_t)(b * 10 + co) * SP + h1 * SS + w1) * 1800 +
                   pos0 * 2 + br;
#pragma unroll
        for (int p = 0; p < 6; p++) {
            float lo, hi;
            UNPACK2(lo, hi, acc[c][p]);     // even-ci + odd-ci partials
            float v = lo + hi + bias;
            d[2 * p] = v > 0.f ? v : 0.f;
        }
    }
}

// ---------------------------------------------------------------------------
// conv3 + final sum: t2 (10 ci, branch-interleaved float2) -> out.
// One CTA per (b,h1,w1), 300 threads = 2 ci-halves x (30 h2 x 5 w2grp(6)).
// smem: 10 planes, 32 rows x 34 float2, left border 2.
// ---------------------------------------------------------------------------
__global__ __launch_bounds__(300, 2)
void conv3_kernel(const float* __restrict__ b3, float* __restrict__ out) {
    extern __shared__ __align__(16) char sm3[];
    ull* sD = (ull*)sm3;                        // 10 * 1088 float2
    ull* sW3 = (ull*)(sm3 + 10 * 1088 * 8);     // 810 (wA,wB)

    int bid = blockIdx.x;
    int b = bid / SP;
    int rem = bid % SP;
    int h1 = rem / SS, w1 = rem % SS;
    int tid = threadIdx.x;

    for (int i = tid; i < 810; i += 300) sW3[i] = ((const ull*)g_W3)[i];
    for (int i = tid; i < 10880; i += 300) sD[i] = 0ull;

    int cihalf = tid / 150;
    int r = tid % 150;
    int h2 = r / 5;
    int w2_0 = (r % 5) * 6;
    int ci0 = cihalf * 5;

    // staging role: thread = (ci, row), full row of 15 chunks
    int sci = tid / 30;
    int srow = tid % 30;
    const float2* tb2 = (const float2*)g_t2 + (size_t)b * 10 * (size_t)SP * SP;
    size_t gRow = (size_t)sci * S4 + srow * 30;
    uint32_t sRow = s2u(sD) + (uint32_t)(sci * 1088 + (srow + 1) * 34 + 2) * 8;

    ull acc[6];
#pragma unroll
    for (int p = 0; p < 6; p++) acc[p] = 0ull;

#pragma unroll 1
    for (int to = 0; to < 9; to++) {
        int H = h1 + to / 3 - 1, W = w1 + to % 3 - 1;
        bool ok = ((unsigned)H < SS) && ((unsigned)W < SS);
        int srcsz = ok ? 16 : 0;
        int poff = ok ? (H * SS + W) : 0;
        __syncthreads();
        const float2* g = tb2 + gRow + (size_t)poff * SP;
#pragma unroll
        for (int k = 0; k < 15; k++)
            cpa16(sRow + k * 16, g + k * 2, srcsz);
        cpa_commit_wait();
        __syncthreads();
#pragma unroll 1
        for (int cc2 = 0; cc2 < 5; cc2++) {
            int ci = ci0 + cc2;
            const ull* sc = sD + ci * 1088;
            const ull* wci = sW3 + (to * 10 + ci) * 9;
#pragma unroll
            for (int dh2 = 0; dh2 < 3; dh2++) {
                const ull* rowp = sc + (h2 + dh2) * 34 + 1 + w2_0;
                ull a[8];
#pragma unroll
                for (int j = 0; j < 8; j++) a[j] = rowp[j];
#pragma unroll
                for (int dw2 = 0; dw2 < 3; dw2++) {
                    ull w = wci[dh2 * 3 + dw2];
#pragma unroll
                    for (int p = 0; p < 6; p++) FMA2(acc[p], a[p + dw2], w);
                }
            }
        }
    }

    // reduce ci-halves via smem (reuse sD)
    __syncthreads();
    ull* red = (ull*)sD;
    if (cihalf) {
#pragma unroll
        for (int p = 0; p < 6; p++) red[r * 6 + p] = acc[p];
    }
    __syncthreads();
    if (!cihalf) {
        float bv = b3[0];
        float* dst = out + (size_t)b * S4 + (h1 * SS + w1) * SP + h2 * SS + w2_0;
#pragma unroll
        for (int p = 0; p < 6; p++) {
            ull o = red[r * 6 + p];
            ADD2(acc[p], acc[p], o);
            float lo, hi;
            UNPACK2(lo, hi, acc[p]);
            float va = lo + bv;
            va = va > 0.f ? va : 0.f;
            float vb = hi + bv;
            vb = vb > 0.f ? vb : 0.f;
            dst[p] = va + vb;
        }
    }
}

// ---------------------------------------------------------------------------
extern "C" void kernel_launch(void* const* d_in, const int* in_sizes, int n_in,
                              void* d_out, int out_size) {
    const float* x = (const float*)d_in[0];
    const float* w1 = (const float*)d_in[1];
    const float* b1 = (const float*)d_in[2];
    const float* w2 = (const float*)d_in[3];
    const float* b2 = (const float*)d_in[4];
    const float* w3 = (const float*)d_in[5];
    const float* b3 = (const float*)d_in[6];
    float* out = (float*)d_out;

    const int smem2 = 5 * 1088 * 8 + 8100 * 4;    // 43520 + 32400 = 75920 B
    const int smem3 = 10 * 1088 * 8 + 810 * 8;    // 87040 + 6480 = 93520 B
    cudaFuncSetAttribute(conv2_kernel,
                         cudaFuncAttributeMaxDynamicSharedMemorySize, smem2);
    cudaFuncSetAttribute(conv3_kernel,
                         cudaFuncAttributeMaxDynamicSharedMemorySize, smem3);

    prep_kernel<<<32, 256>>>(w1, w2, w3);
    conv1_kernel<<<NB * SP, 300>>>(x, b1);
    conv2_kernel<<<NB * 2 * SP, 300, smem2>>>(b2);
    conv3_kernel<<<NB * SP, 300, smem3>>>(b3, out);
}

// round 5
// speedup vs baseline: 1.0752x; 1.0752x over previous
#include <cuda_runtime.h>
#include <cstdint>

#define SS 30
#define SP 900          // 30*30
#define S4 810000       // 30^4
#define NB 2

typedef unsigned long long ull;

// t1: [b][br][cipair5][h1w1][pos][2]  (lanes = ci even/odd)  — float2 elements
__device__ __align__(16) float g_t1[NB * 2 * 5 * SP * SP * 2];
// t2: [b][co10][h1w1][pos][br2]  — float2 elements (lanes = branch A/B)
__device__ __align__(16) float g_t2[NB * 10 * SP * SP * 2];
// Weights
__device__ __align__(16) float g_W1[9 * 9 * 20];                 // [to][ti][co20]
__device__ __align__(16) float g_W2[2 * 9 * 5 * 9 * 10 * 2];     // [br][to][cp][ti][co][ci-lane]
__device__ __align__(16) float g_W3[9 * 10 * 9 * 2];             // [to][ci][ti][br2]

#define PACK2(d, a, b)  asm("mov.b64 %0, {%1, %2};" : "=l"(d) : "f"(a), "f"(b))
#define FMA2(d, a, b)   asm("fma.rn.f32x2 %0, %1, %2, %0;" : "+l"(d) : "l"(a), "l"(b))
#define ADD2(d, a, b)   asm("add.rn.f32x2 %0, %1, %2;" : "=l"(d) : "l"(a), "l"(b))
#define UNPACK2(lo, hi, d) asm("mov.b64 {%0, %1}, %2;" : "=f"(lo), "=f"(hi) : "l"(d))

__device__ __forceinline__ uint32_t s2u(const void* p) {
    uint32_t a;
    asm("{ .reg .u64 t; cvta.to.shared.u64 t, %1; cvt.u32.u64 %0, t; }"
        : "=r"(a) : "l"(p));
    return a;
}
__device__ __forceinline__ void cpa4(uint32_t s, const void* g, int srcsz) {
    asm volatile("cp.async.ca.shared.global [%0], [%1], 4, %2;"
                 :: "r"(s), "l"(g), "r"(srcsz));
}
__device__ __forceinline__ void cpa16(uint32_t s, const void* g, int srcsz) {
    asm volatile("cp.async.ca.shared.global [%0], [%1], 16, %2;"
                 :: "r"(s), "l"(g), "r"(srcsz));
}
__device__ __forceinline__ void cpa_commit_wait() {
    asm volatile("cp.async.commit_group;");
    asm volatile("cp.async.wait_group 0;" ::: "memory");
}

// ---------------------------------------------------------------------------
// Weight prep.
// ---------------------------------------------------------------------------
__global__ void prep_kernel(const float* __restrict__ w1,
                            const float* __restrict__ w2,
                            const float* __restrict__ w3) {
    int tid = blockIdx.x * blockDim.x + threadIdx.x;
    int stride = gridDim.x * blockDim.x;
    for (int i = tid; i < 9 * 9 * 20; i += stride) {
        int co = i % 20;
        int ti = (i / 20) % 9;
        int to = i / 180;
        g_W1[i] = (co < 10) ? w1[co * 81 + to * 9 + ti]
                            : w1[(co - 10) * 81 + ti * 9 + to];
    }
    // W2: [br][to][cp][ti][co][lane], lane = ci parity, ci = 2*cp+lane
    for (int i = tid; i < 16200; i += stride) {
        int lane = i & 1;
        int j = i >> 1;
        int co = j % 10;
        int ti = (j / 10) % 9;
        int cp = (j / 90) % 5;
        int to = (j / 450) % 9;
        int br = j / 4050;
        int ci = 2 * cp + lane;
        int tap = br ? (ti * 9 + to) : (to * 9 + ti);
        g_W2[i] = w2[(co * 10 + ci) * 81 + tap];
    }
    for (int i = tid; i < 1620; i += stride) {
        int br = i % 2;
        int ti = (i / 2) % 9;
        int ci = (i / 18) % 10;
        int to = i / 180;
        g_W3[i] = (br == 0) ? w3[ci * 81 + to * 9 + ti]
                            : w3[ci * 81 + ti * 9 + to];
    }
}

// ---------------------------------------------------------------------------
// conv1: x (1 ch) -> t1 (ci-pair interleaved), relu.  One CTA per (b,h1,w1).
// ---------------------------------------------------------------------------
__global__ __launch_bounds__(300)
void conv1_kernel(const float* __restrict__ x, const float* __restrict__ b1) {
    __shared__ __align__(16) float sIn[32 * 33];
    __shared__ __align__(16) float sW[9 * 9 * 20];
    __shared__ float sB[20];
    int bid = blockIdx.x;
    int b = bid / SP;
    int rem = bid % SP;
    int h1 = rem / SS, w1 = rem % SS;
    int tid = threadIdx.x;

    {
        const float4* src = (const float4*)g_W1;
        float4* dst = (float4*)sW;
        for (int i = tid; i < 405; i += 300) dst[i] = src[i];
    }
    if (tid < 20) sB[tid] = b1[tid % 10];
    for (int i = tid; i < 32 * 33; i += 300) sIn[i] = 0.f;

    int h2 = tid / 10;
    int w2_0 = (tid % 10) * 3;

    int gOff[3], sOff[3];
#pragma unroll
    for (int k = 0; k < 3; k++) {
        int j = tid + k * 300;
        int rr = j / SS, cc = j % SS;
        gOff[k] = j;
        sOff[k] = (rr + 1) * 33 + cc + 1;
    }
    uint32_t sInA = s2u(sIn);

    ull acc[10][3];
#pragma unroll
    for (int c = 0; c < 10; c++)
#pragma unroll
        for (int p = 0; p < 3; p++) acc[c][p] = 0ull;

    const float* xb = x + (size_t)b * S4;

#pragma unroll 1
    for (int to = 0; to < 9; to++) {
        int H = h1 + to / 3 - 1, W = w1 + to % 3 - 1;
        bool ok = ((unsigned)H < SS) && ((unsigned)W < SS);
        int srcsz = ok ? 4 : 0;
        int poff = ok ? (H * SS + W) * SP : 0;
        const float* plane = xb + poff;
        __syncthreads();
#pragma unroll
        for (int k = 0; k < 3; k++)
            cpa4(sInA + sOff[k] * 4, plane + gOff[k], srcsz);
        cpa_commit_wait();
        __syncthreads();
#pragma unroll
        for (int dh2 = 0; dh2 < 3; dh2++) {
            const float* row = &sIn[(h2 + dh2) * 33 + w2_0];
            ull dup[5];
#pragma unroll
            for (int j = 0; j < 5; j++) { float v = row[j]; PACK2(dup[j], v, v); }
#pragma unroll
            for (int dw2 = 0; dw2 < 3; dw2++) {
                const ull* wp = (const ull*)(sW + (to * 9 + dh2 * 3 + dw2) * 20);
#pragma unroll
                for (int c = 0; c < 10; c++) {
                    ull w = wp[c];
#pragma unroll
                    for (int p = 0; p < 3; p++) FMA2(acc[c][p], dup[p + dw2], w);
                }
            }
        }
    }

    // store: pair c -> (br = c/5, cp = c%5), lanes = (co even, co odd) = ci lanes of t1
#pragma unroll
    for (int c = 0; c < 10; c++) {
        int br = c / 5, cp = c % 5;
        float b0 = sB[2 * c], b1v = sB[2 * c + 1];
        float2* d = (float2*)g_t1 +
                    (((size_t)(b * 2 + br) * 5 + cp) * SP + h1 * SS + w1) * SP +
                    h2 * SS + w2_0;
#pragma unroll
        for (int p = 0; p < 3; p++) {
            float lo, hi;
            UNPACK2(lo, hi, acc[c][p]);
            lo += b0; hi += b1v;
            d[p] = make_float2(lo > 0.f ? lo : 0.f, hi > 0.f ? hi : 0.f);
        }
    }
}

// ---------------------------------------------------------------------------
// conv2: t1 (ci-pair float2) -> t2 (branch-interleaved), relu.
// One CTA per (b, br, h1, w1), 300 threads = 2 co-halves x (30 h2 x 5 w2grp(6)).
// Staging: 60 threads/plane, thread t takes 16B chunks t + k*60 (coalesced),
// smem dst affine in k (row = 4k + t/15, col = (2t)%30).
// ---------------------------------------------------------------------------
__global__ __launch_bounds__(300, 2)
void conv2_kernel(const float* __restrict__ b2) {
    extern __shared__ __align__(16) char sm2[];
    ull* sIn = (ull*)sm2;                       // 5 * 1088 float2
    float* sW = (float*)(sm2 + 5 * 1088 * 8);   // 8100 floats
    __shared__ float sB[10];

    int bid = blockIdx.x;
    int w1 = bid % SS;
    int t = bid / SS;
    int h1 = t % SS;
    t /= SS;
    int br = t & 1;
    int b = t >> 1;
    int tid = threadIdx.x;

    {
        const float4* src = (const float4*)(g_W2 + br * 8100);
        float4* dst = (float4*)sW;
        for (int i = tid; i < 2025; i += 300) dst[i] = src[i];
    }
    if (tid < 10) sB[tid] = b2[tid];
    for (int i = tid; i < 5440; i += 300) sIn[i] = 0ull;

    int cohalf = tid / 150;
    int r = tid % 150;
    int h2 = r / 5;
    int w2_0 = (r % 5) * 6;
    int co0 = cohalf * 5;

    // staging role: plane scp = tid/60, within-plane thread t60 = tid%60.
    // chunk(k) = t60 + k*60 (k=0..7, chunk<450); off(float2) = 2*t60 + 120k;
    // row = 4k + t60/15, col = (2*t60)%30.
    int scp = tid / 60;
    int t60 = tid % 60;
    int r0 = t60 / 15;
    int col2 = (2 * t60) % 30;
    int kmax = (t60 < 30) ? 8 : 7;   // 450 chunks / 60 threads
    uint32_t sBase = s2u(sIn) +
                     (uint32_t)(scp * 1088 + (r0 + 1) * 34 + 2 + col2) * 8;
    const float2* t1f2 = (const float2*)g_t1 + (size_t)(b * 2 + br) * 5 * (size_t)S4;
    size_t gBase = (size_t)scp * S4 + 2 * t60;

    ull acc[5][6];
#pragma unroll
    for (int c = 0; c < 5; c++)
#pragma unroll
        for (int p = 0; p < 6; p++) acc[c][p] = 0ull;

#pragma unroll 1
    for (int to = 0; to < 9; to++) {
        int H = h1 + to / 3 - 1, W = w1 + to % 3 - 1;
        bool ok = ((unsigned)H < SS) && ((unsigned)W < SS);
        int srcsz = ok ? 16 : 0;
        int poff = ok ? (H * SS + W) : 0;
        __syncthreads();
        const float2* g = t1f2 + gBase + (size_t)poff * SP;
#pragma unroll
        for (int k = 0; k < 8; k++)
            if (k < kmax) cpa16(sBase + k * (136 * 8), g + k * 120, srcsz);
        cpa_commit_wait();
        __syncthreads();
#pragma unroll 1
        for (int cp = 0; cp < 5; cp++) {
            const ull* sc = sIn + cp * 1088;
            const ull* wbase = (const ull*)sW + (to * 5 + cp) * 90;
#pragma unroll
            for (int dh2 = 0; dh2 < 3; dh2++) {
                const ull* rowp = sc + (h2 + dh2) * 34 + 1 + w2_0;
                ull a[8];
#pragma unroll
                for (int j = 0; j < 8; j++) a[j] = rowp[j];
#pragma unroll
                for (int dw2 = 0; dw2 < 3; dw2++) {
                    const ull* wp = wbase + (dh2 * 3 + dw2) * 10 + co0;
#pragma unroll
                    for (int c = 0; c < 5; c++) {
                        ull w = wp[c];
#pragma unroll
                        for (int p = 0; p < 6; p++) FMA2(acc[c][p], a[p + dw2], w);
                    }
                }
            }
        }
    }

    int pos0 = h2 * SS + w2_0;
#pragma unroll
    for (int c = 0; c < 5; c++) {
        int co = co0 + c;
        float bias = sB[co];
        float* d = g_t2 + ((size_t)(b * 10 + co) * SP + h1 * SS + w1) * 1800 +
                   pos0 * 2 + br;
#pragma unroll
        for (int p = 0; p < 6; p++) {
            float lo, hi;
            UNPACK2(lo, hi, acc[c][p]);     // even-ci + odd-ci partials
            float v = lo + hi + bias;
            d[2 * p] = v > 0.f ? v : 0.f;
        }
    }
}

// ---------------------------------------------------------------------------
// conv3 + final sum: t2 (10 ci, branch-interleaved float2) -> out.
// One CTA per (b,h1,w1), 300 threads = 2 ci-halves x (30 h2 x 5 w2grp(6)).
// Staging: 30 threads/plane, thread t takes 16B chunks t + k*30 (coalesced),
// smem dst affine in k (row = 2k + t/15, col = (2t)%30).
// ---------------------------------------------------------------------------
__global__ __launch_bounds__(300, 2)
void conv3_kernel(const float* __restrict__ b3, float* __restrict__ out) {
    extern __shared__ __align__(16) char sm3[];
    ull* sD = (ull*)sm3;                        // 10 * 1088 float2
    ull* sW3 = (ull*)(sm3 + 10 * 1088 * 8);     // 810 (wA,wB)

    int bid = blockIdx.x;
    int b = bid / SP;
    int rem = bid % SP;
    int h1 = rem / SS, w1 = rem % SS;
    int tid = threadIdx.x;

    for (int i = tid; i < 810; i += 300) sW3[i] = ((const ull*)g_W3)[i];
    for (int i = tid; i < 10880; i += 300) sD[i] = 0ull;

    int cihalf = tid / 150;
    int r = tid % 150;
    int h2 = r / 5;
    int w2_0 = (r % 5) * 6;
    int ci0 = cihalf * 5;

    // staging role: plane sci = tid/30, t30 = tid%30; chunk(k) = t30 + 30k,
    // k = 0..14; off = 2*t30 + 60k; row = 2k + t30/15, col = (2*t30)%30.
    int sci = tid / 30;
    int t30 = tid % 30;
    int r0 = t30 / 15;
    int col2 = (2 * t30) % 30;
    uint32_t sBase = s2u(sD) +
                     (uint32_t)(sci * 1088 + (r0 + 1) * 34 + 2 + col2) * 8;
    const float2* tb2 = (const float2*)g_t2 + (size_t)b * 10 * (size_t)SP * SP;
    size_t gBase = (size_t)sci * S4 + 2 * t30;

    ull acc[6];
#pragma unroll
    for (int p = 0; p < 6; p++) acc[p] = 0ull;

#pragma unroll 1
    for (int to = 0; to < 9; to++) {
        int H = h1 + to / 3 - 1, W = w1 + to % 3 - 1;
        bool ok = ((unsigned)H < SS) && ((unsigned)W < SS);
        int srcsz = ok ? 16 : 0;
        int poff = ok ? (H * SS + W) : 0;
        __syncthreads();
        const float2* g = tb2 + gBase + (size_t)poff * SP;
#pragma unroll
        for (int k = 0; k < 15; k++)
            cpa16(sBase + k * (68 * 8), g + k * 60, srcsz);
        cpa_commit_wait();
        __syncthreads();
#pragma unroll 1
        for (int cc2 = 0; cc2 < 5; cc2++) {
            int ci = ci0 + cc2;
            const ull* sc = sD + ci * 1088;
            const ull* wci = sW3 + (to * 10 + ci) * 9;
#pragma unroll
            for (int dh2 = 0; dh2 < 3; dh2++) {
                const ull* rowp = sc + (h2 + dh2) * 34 + 1 + w2_0;
                ull a[8];
#pragma unroll
                for (int j = 0; j < 8; j++) a[j] = rowp[j];
#pragma unroll
                for (int dw2 = 0; dw2 < 3; dw2++) {
                    ull w = wci[dh2 * 3 + dw2];
#pragma unroll
                    for (int p = 0; p < 6; p++) FMA2(acc[p], a[p + dw2], w);
                }
            }
        }
    }

    // reduce ci-halves via smem (reuse sD)
    __syncthreads();
    ull* red = (ull*)sD;
    if (cihalf) {
#pragma unroll
        for (int p = 0; p < 6; p++) red[r * 6 + p] = acc[p];
    }
    __syncthreads();
    if (!cihalf) {
        float bv = b3[0];
        float* dst = out + (size_t)b * S4 + (h1 * SS + w1) * SP + h2 * SS + w2_0;
#pragma unroll
        for (int p = 0; p < 6; p++) {
            ull o = red[r * 6 + p];
            ADD2(acc[p], acc[p], o);
            float lo, hi;
            UNPACK2(lo, hi, acc[p]);
            float va = lo + bv;
            va = va > 0.f ? va : 0.f;
            float vb = hi + bv;
            vb = vb > 0.f ? vb : 0.f;
            dst[p] = va + vb;
        }
    }
}

// ---------------------------------------------------------------------------
extern "C" void kernel_launch(void* const* d_in, const int* in_sizes, int n_in,
                              void* d_out, int out_size) {
    const float* x = (const float*)d_in[0];
    const float* w1 = (const float*)d_in[1];
    const float* b1 = (const float*)d_in[2];
    const float* w2 = (const float*)d_in[3];
    const float* b2 = (const float*)d_in[4];
    const float* w3 = (const float*)d_in[5];
    const float* b3 = (const float*)d_in[6];
    float* out = (float*)d_out;

    const int smem2 = 5 * 1088 * 8 + 8100 * 4;    // 75920 B
    const int smem3 = 10 * 1088 * 8 + 810 * 8;    // 93520 B
    cudaFuncSetAttribute(conv2_kernel,
                         cudaFuncAttributeMaxDynamicSharedMemorySize, smem2);
    cudaFuncSetAttribute(conv3_kernel,
                         cudaFuncAttributeMaxDynamicSharedMemorySize, smem3);

    prep_kernel<<<32, 256>>>(w1, w2, w3);
    conv1_kernel<<<NB * SP, 300>>>(x, b1);
    conv2_kernel<<<NB * 2 * SP, 300, smem2>>>(b2);
    conv3_kernel<<<NB * SP, 300, smem3>>>(b3, out);
}